// round 14
// baseline (speedup 1.0000x reference)
#include <cuda_runtime.h>

// PlaneEmbeddingNetwork fused kernel for GB300 (sm_103a), R14.
// = R13 (best: 141.4us) + three instruction trims:
//  1) 1/sqrt(8) score scale folded into q-columns of s_win/s_bin at fill time
//  2) softmax max-subtraction removed (|score| <~ 10, exp is safe)
//  3) softmax reciprocal via __fdividef (MUFU.RCP)
// Memory system, register pressure, and layout identical to R13.

typedef unsigned long long u64;

__device__ __forceinline__ u64 fma2(u64 a, u64 b, u64 c) {
    u64 d;
    asm("fma.rn.f32x2 %0, %1, %2, %3;" : "=l"(d) : "l"(a), "l"(b), "l"(c));
    return d;
}
__device__ __forceinline__ u64 pack2(float x, float y) {
    u64 r;
    asm("mov.b64 %0, {%1, %2};" : "=l"(r) : "f"(x), "f"(y));
    return r;
}
__device__ __forceinline__ float2 unpack2(u64 v) {
    float2 f;
    asm("mov.b64 {%0, %1}, %2;" : "=f"(f.x), "=f"(f.y) : "l"(v));
    return f;
}
__device__ __forceinline__ float getc(float4 v, int c) {
    return c == 0 ? v.x : (c == 1 ? v.y : (c == 2 ? v.z : v.w));
}

// Fused weights computed once by prep kernel:
//   W2[d][j] = sum_e w_out[d][e] * fc_w[e][j]    (16 x 32)
//   b2[j]    = fc_b[j] + sum_e b_out[e] * fc_w[e][j]
__device__ float g_W2[16 * 32];
__device__ float g_b2[32];

__global__ void prep_kernel(const float* __restrict__ w_out, const float* __restrict__ b_out,
                            const float* __restrict__ fc_w, const float* __restrict__ fc_b) {
    int i = threadIdx.x;
    if (i < 512) {
        int d = i >> 5, j = i & 31;
        float s = 0.f;
#pragma unroll
        for (int e = 0; e < 16; e++) s += w_out[d * 16 + e] * fc_w[e * 32 + j];
        g_W2[i] = s;
    }
    if (i < 32) {
        float s = fc_b[i];
#pragma unroll
        for (int e = 0; e < 16; e++) s += b_out[e] * fc_w[e * 32 + i];
        g_b2[i] = s;
    }
}

__global__ void __launch_bounds__(128, 4)
face_kernel(const float* __restrict__ node, const int* __restrict__ fids,
            const float* __restrict__ w_in, const float* __restrict__ b_in,
            const float* __restrict__ fco_w, const float* __restrict__ fco_b,
            float* __restrict__ out, int F) {
    __shared__ __align__(16) float s_win[16 * 48];   // packed qkv weights [d][o], q-cols pre-scaled
    __shared__ __align__(16) float s_bin[48];
    __shared__ __align__(16) float s_W2[16 * 32];    // fused w_out@fc_w
    __shared__ __align__(16) float s_b2[32];
    __shared__ __align__(16) float s_fco[32 * 32];
    __shared__ __align__(16) float s_fcob[32];
    __shared__ __align__(16) float s_stage[4][8][132];  // [warp][slot][quad*16+chunk*4]

    const float RS = 0.35355339059327373f;  // 1/sqrt(8), folded into q weights

    int tid = threadIdx.x;
    int gt = blockIdx.x * 128 + tid;
    int faceR = gt >> 1;            // real face (may be >= F for tail lanes)
    int h = gt & 1;                 // head index (0 or 1)
    bool valid = faceR < F;
    int face = valid ? faceR : (F - 1);  // clamped for loads

    int lane = tid & 31;
    int wq = lane >> 2;             // quad index within warp (0..7)
    int ql = lane & 3;              // lane within quad

    // ---- gather FIRST: fids + 8 node LDGs in flight before weight fills ----
    int4 Im = *(const int4*)(fids + 4ll * face);
    int ox = __shfl_xor_sync(0xffffffffu, Im.x, 2);
    int oy = __shfl_xor_sync(0xffffffffu, Im.y, 2);
    int oz = __shfl_xor_sync(0xffffffffu, Im.z, 2);
    int ow = __shfl_xor_sync(0xffffffffu, Im.w, 2);
    bool isB = (lane & 2) != 0;
    int IAx = isB ? ox : Im.x, IAy = isB ? oy : Im.y;
    int IAz = isB ? oz : Im.z, IAw = isB ? ow : Im.w;
    int IBx = isB ? Im.x : ox, IBy = isB ? Im.y : oy;
    int IBz = isB ? Im.z : oz, IBw = isB ? Im.w : ow;
    long long co = 4 * ql;          // chunk offset in floats
    float4 r0 = *(const float4*)(node + 16ll * IAx + co);
    float4 r1 = *(const float4*)(node + 16ll * IAz + co);
    float4 r2 = *(const float4*)(node + 16ll * IBx + co);
    float4 r3 = *(const float4*)(node + 16ll * IBz + co);
    float4 r4 = *(const float4*)(node + 16ll * IAy + co);
    float4 r5 = *(const float4*)(node + 16ll * IAw + co);
    float4 r6 = *(const float4*)(node + 16ll * IBy + co);
    float4 r7 = *(const float4*)(node + 16ll * IBw + co);

    // ---- weight smem fills overlap the gather latency ----
    // q-columns (col%48 < 16) pre-scaled by RS: scores then need no scaling.
    for (int i = tid; i < 768; i += 128) {
        float w = w_in[i];
        s_win[i] = ((i % 48) < 16) ? w * RS : w;
    }
    if (tid < 48) {
        float b = b_in[tid];
        s_bin[tid] = (tid < 16) ? b * RS : b;
    }
    for (int i = tid; i < 512; i += 128) s_W2[i] = g_W2[i];
    if (tid < 32) s_b2[tid] = g_b2[tid];
    for (int i = tid; i < 1024; i += 128) s_fco[i] = fco_w[i];
    if (tid < 32) s_fcob[tid] = fco_b[tid];

    // ---- stage-store + warp-local redistribution (no block barrier needed) ----
    float* st = &s_stage[tid >> 5][0][0];
    {
        int so = wq * 16 + ql * 4;
        *(float4*)(st + 0 * 132 + so) = r0;
        *(float4*)(st + 1 * 132 + so) = r1;
        *(float4*)(st + 2 * 132 + so) = r2;
        *(float4*)(st + 3 * 132 + so) = r3;
        *(float4*)(st + 4 * 132 + so) = r4;
        *(float4*)(st + 5 * 132 + so) = r5;
        *(float4*)(st + 6 * 132 + so) = r6;
        *(float4*)(st + 7 * 132 + so) = r7;
    }
    __syncwarp();
    float4 XA[4], XB[4];
    {
        const float* pa = st + ql * 132 + wq * 16;
        const float* pb = st + (ql + 4) * 132 + wq * 16;
#pragma unroll
        for (int cc = 0; cc < 4; cc++) {
            XA[cc] = *(const float4*)(pa + cc * 4);
            XB[cc] = *(const float4*)(pb + cc * 4);
        }
    }

    __syncthreads();   // weights ready before first use

    // Lane-local token order: 0 = own_a, 1 = own_b, 2 = partner_a, 3 = partner_b.

    // ---- phase 1a: q,k for all 4 tokens (own head), d-outer for weight reuse ----
    u64 q2[4][4], k2[4][4];
    {
        const u64* bq = (const u64*)(s_bin + 8 * h);
        const u64* bk = (const u64*)(s_bin + 16 + 8 * h);
#pragma unroll
        for (int t = 0; t < 4; t++)
#pragma unroll
            for (int j = 0; j < 4; j++) { q2[t][j] = bq[j]; k2[t][j] = bk[j]; }
    }
    {
        const float* wqp = s_win + 8 * h;
        const float* wkp = s_win + 16 + 8 * h;
#pragma unroll
        for (int d = 0; d < 16; d++) {
            ulonglong2 wq0 = *(const ulonglong2*)(wqp + d * 48);
            ulonglong2 wq1 = *(const ulonglong2*)(wqp + d * 48 + 4);
            ulonglong2 wk0 = *(const ulonglong2*)(wkp + d * 48);
            ulonglong2 wk1 = *(const ulonglong2*)(wkp + d * 48 + 4);
            float xa = getc(XA[d >> 2], d & 3);
            float xb = getc(XB[d >> 2], d & 3);
            float fa = __shfl_xor_sync(0xffffffffu, xa, 1);
            float fb = __shfl_xor_sync(0xffffffffu, xb, 1);
            u64 xt[4] = {pack2(xa, xa), pack2(xb, xb), pack2(fa, fa), pack2(fb, fb)};
#pragma unroll
            for (int t = 0; t < 4; t++) {
                q2[t][0] = fma2(xt[t], wq0.x, q2[t][0]);
                q2[t][1] = fma2(xt[t], wq0.y, q2[t][1]);
                q2[t][2] = fma2(xt[t], wq1.x, q2[t][2]);
                q2[t][3] = fma2(xt[t], wq1.y, q2[t][3]);
                k2[t][0] = fma2(xt[t], wk0.x, k2[t][0]);
                k2[t][1] = fma2(xt[t], wk0.y, k2[t][1]);
                k2[t][2] = fma2(xt[t], wk1.x, k2[t][2]);
                k2[t][3] = fma2(xt[t], wk1.y, k2[t][3]);
            }
        }
    }

    // ---- scores + softmax (own head, 4x4; scale pre-folded; no max-sub) ----
    float att[4][4];
#pragma unroll
    for (int qi = 0; qi < 4; qi++) {
#pragma unroll
        for (int ki = 0; ki < 4; ki++) {
            u64 a = fma2(q2[qi][0], k2[ki][0], 0ull);
            a = fma2(q2[qi][1], k2[ki][1], a);
            a = fma2(q2[qi][2], k2[ki][2], a);
            a = fma2(q2[qi][3], k2[ki][3], a);
            float2 p = unpack2(a);
            att[qi][ki] = p.x + p.y;
        }
        float e0 = __expf(att[qi][0]);
        float e1 = __expf(att[qi][1]);
        float e2 = __expf(att[qi][2]);
        float e3 = __expf(att[qi][3]);
        float inv = __fdividef(1.0f, e0 + e1 + e2 + e3);
        att[qi][0] = e0 * inv; att[qi][1] = e1 * inv;
        att[qi][2] = e2 * inv; att[qi][3] = e3 * inv;
    }

    // ---- phase 1b: v for all 4 tokens (own head), d-outer ----
    u64 v2[4][4];
    {
        const u64* bv = (const u64*)(s_bin + 32 + 8 * h);
#pragma unroll
        for (int t = 0; t < 4; t++)
#pragma unroll
            for (int j = 0; j < 4; j++) v2[t][j] = bv[j];
    }
    {
        const float* wvp = s_win + 32 + 8 * h;
#pragma unroll
        for (int d = 0; d < 16; d++) {
            ulonglong2 wv0 = *(const ulonglong2*)(wvp + d * 48);
            ulonglong2 wv1 = *(const ulonglong2*)(wvp + d * 48 + 4);
            float xa = getc(XA[d >> 2], d & 3);
            float xb = getc(XB[d >> 2], d & 3);
            float fa = __shfl_xor_sync(0xffffffffu, xa, 1);
            float fb = __shfl_xor_sync(0xffffffffu, xb, 1);
            u64 xt[4] = {pack2(xa, xa), pack2(xb, xb), pack2(fa, fa), pack2(fb, fb)};
#pragma unroll
            for (int t = 0; t < 4; t++) {
                v2[t][0] = fma2(xt[t], wv0.x, v2[t][0]);
                v2[t][1] = fma2(xt[t], wv0.y, v2[t][1]);
                v2[t][2] = fma2(xt[t], wv1.x, v2[t][2]);
                v2[t][3] = fma2(xt[t], wv1.y, v2[t][3]);
            }
        }
    }

    // ---- o = attn @ v for all 4 local query tokens (own head half: 8 dims) ----
    u64 o2[4][4];
#pragma unroll
    for (int qi = 0; qi < 4; qi++) {
#pragma unroll
        for (int j = 0; j < 4; j++) o2[qi][j] = 0ull;
#pragma unroll
        for (int s = 0; s < 4; s++) {
            u64 a2 = pack2(att[qi][s], att[qi][s]);
#pragma unroll
            for (int j = 0; j < 4; j++) o2[qi][j] = fma2(a2, v2[s][j], o2[qi][j]);
        }
    }

    // ---- W2 col-split with PROGRESSIVE o-exchange ----
    u64 acc[4][8];
    {
        const u64* bb = (const u64*)(s_b2 + 16 * h);
#pragma unroll
        for (int t = 0; t < 4; t++)
#pragma unroll
            for (int j = 0; j < 8; j++) acc[t][j] = bb[j];
    }
    {
        const float* wbaseA = s_W2 + (8 * h) * 32 + 16 * h;
#pragma unroll
        for (int dd = 0; dd < 8; dd++) {
            const ulonglong2* wr = (const ulonglong2*)(wbaseA + dd * 32);
            ulonglong2 wa = wr[0], wb = wr[1], wc = wr[2], wd_ = wr[3];
#pragma unroll
            for (int t = 0; t < 4; t++) {
                float2 p = unpack2(o2[t][dd >> 1]);
                float ov = (dd & 1) ? p.y : p.x;
                u64 op = pack2(ov, ov);
                acc[t][0] = fma2(op, wa.x, acc[t][0]);
                acc[t][1] = fma2(op, wa.y, acc[t][1]);
                acc[t][2] = fma2(op, wb.x, acc[t][2]);
                acc[t][3] = fma2(op, wb.y, acc[t][3]);
                acc[t][4] = fma2(op, wc.x, acc[t][4]);
                acc[t][5] = fma2(op, wc.y, acc[t][5]);
                acc[t][6] = fma2(op, wd_.x, acc[t][6]);
                acc[t][7] = fma2(op, wd_.y, acc[t][7]);
            }
        }
    }
    u64 rcv[4][4];
#pragma unroll
    for (int t = 0; t < 4; t++)
#pragma unroll
        for (int j = 0; j < 4; j++)
            rcv[t][j] = __shfl_xor_sync(0xffffffffu, o2[t ^ 2][j], 1);
    {
        const float* wbaseB = s_W2 + (8 * (1 - h)) * 32 + 16 * h;
#pragma unroll
        for (int dd = 0; dd < 8; dd++) {
            const ulonglong2* wr = (const ulonglong2*)(wbaseB + dd * 32);
            ulonglong2 wa = wr[0], wb = wr[1], wc = wr[2], wd_ = wr[3];
#pragma unroll
            for (int t = 0; t < 4; t++) {
                float2 p = unpack2(rcv[t][dd >> 1]);
                float ov = (dd & 1) ? p.y : p.x;
                u64 op = pack2(ov, ov);
                acc[t][0] = fma2(op, wa.x, acc[t][0]);
                acc[t][1] = fma2(op, wa.y, acc[t][1]);
                acc[t][2] = fma2(op, wb.x, acc[t][2]);
                acc[t][3] = fma2(op, wb.y, acc[t][3]);
                acc[t][4] = fma2(op, wc.x, acc[t][4]);
                acc[t][5] = fma2(op, wc.y, acc[t][5]);
                acc[t][6] = fma2(op, wd_.x, acc[t][6]);
                acc[t][7] = fma2(op, wd_.y, acc[t][7]);
            }
        }
    }

    // ---- relu + mean over 4 tokens (thread-local) ----
    u64 pool[8];   // my 16 cols
#pragma unroll
    for (int j = 0; j < 8; j++) {
        float px = 0.f, py = 0.f;
#pragma unroll
        for (int t = 0; t < 4; t++) {
            float2 a = unpack2(acc[t][j]);
            px += fmaxf(a.x, 0.f);
            py += fmaxf(a.y, 0.f);
        }
        pool[j] = pack2(px * 0.25f, py * 0.25f);
    }

    // ---- butterfly: full 32 pooled for own face (xor1), then partner face (xor2) ----
    u64 pown[16];
#pragma unroll
    for (int j = 0; j < 8; j++) {
        u64 other = __shfl_xor_sync(0xffffffffu, pool[j], 1);
        pown[j]     = h ? other : pool[j];
        pown[8 + j] = h ? pool[j] : other;
    }
    u64 poth[16];
#pragma unroll
    for (int j = 0; j < 16; j++)
        poth[j] = __shfl_xor_sync(0xffffffffu, pown[j], 2);

    // ---- fco quad-split: col octet [8c, 8c+8), c = tid&3, for BOTH quad faces ----
    int c = tid & 3;
    u64 accA[4], accB[4];
    {
        const u64* fb = (const u64*)(s_fcob + 8 * c);
#pragma unroll
        for (int p = 0; p < 4; p++) { accA[p] = fb[p]; accB[p] = fb[p]; }
    }
    const float* fch = s_fco + 8 * c;
#pragma unroll
    for (int e = 0; e < 32; e++) {
        float2 ppA = unpack2(pown[e >> 1]);
        float2 ppB = unpack2(poth[e >> 1]);
        float peA = (e & 1) ? ppA.y : ppA.x;
        float peB = (e & 1) ? ppB.y : ppB.x;
        u64 pA2 = pack2(peA, peA);
        u64 pB2 = pack2(peB, peB);
        const ulonglong2* fr = (const ulonglong2*)(fch + e * 32);
        ulonglong2 wa = fr[0], wb = fr[1];
        accA[0] = fma2(pA2, wa.x, accA[0]);
        accA[1] = fma2(pA2, wa.y, accA[1]);
        accA[2] = fma2(pA2, wb.x, accA[2]);
        accA[3] = fma2(pA2, wb.y, accA[3]);
        accB[0] = fma2(pB2, wa.x, accB[0]);
        accB[1] = fma2(pB2, wa.y, accB[1]);
        accB[2] = fma2(pB2, wb.x, accB[2]);
        accB[3] = fma2(pB2, wb.y, accB[3]);
    }

    // ---- stores: face A = my real face; face B = quad partner's face (^1) ----
    int faceB = faceR ^ 1;
    if (valid) {
        float* opA = out + 32ll * faceR + 8 * c;
        float2 a0 = unpack2(accA[0]), a1 = unpack2(accA[1]);
        float2 a2 = unpack2(accA[2]), a3 = unpack2(accA[3]);
        ((float4*)opA)[0] = make_float4(a0.x, a0.y, a1.x, a1.y);
        ((float4*)opA)[1] = make_float4(a2.x, a2.y, a3.x, a3.y);
    }
    if (faceB < F) {
        float* opB = out + 32ll * faceB + 8 * c;
        float2 b0 = unpack2(accB[0]), b1 = unpack2(accB[1]);
        float2 b2 = unpack2(accB[2]), b3 = unpack2(accB[3]);
        ((float4*)opB)[0] = make_float4(b0.x, b0.y, b1.x, b1.y);
        ((float4*)opB)[1] = make_float4(b2.x, b2.y, b3.x, b3.y);
    }
}

extern "C" void kernel_launch(void* const* d_in, const int* in_sizes, int n_in,
                              void* d_out, int out_size) {
    const float* node  = (const float*)d_in[0];
    const int*   fids  = (const int*)d_in[1];
    const float* w_in  = (const float*)d_in[2];
    const float* b_in  = (const float*)d_in[3];
    const float* w_out = (const float*)d_in[4];
    const float* b_out = (const float*)d_in[5];
    const float* fc_w  = (const float*)d_in[6];
    const float* fc_b  = (const float*)d_in[7];
    const float* fco_w = (const float*)d_in[8];
    const float* fco_b = (const float*)d_in[9];

    int F = in_sizes[1] / 4;

    prep_kernel<<<1, 512>>>(w_out, b_out, fc_w, fc_b);

    long long threads = 2ll * F;
    int blocks = (int)((threads + 127) / 128);
    face_kernel<<<blocks, 128>>>(node, fids, w_in, b_in, fco_w, fco_b, (float*)d_out, F);
}

// round 15
// speedup vs baseline: 1.0305x; 1.0305x over previous
#include <cuda_runtime.h>

// PlaneEmbeddingNetwork fused kernel for GB300 (sm_103a), R15.
// = R13 (best: 141.4us) + ONLY the two subtractive softmax trims from R14:
//  - max-subtraction removed (|score| <~ 10, __expf safe; verified in R14)
//  - reciprocal via __fdividef (MUFU.RCP)
// R14's weight-fill conditional (i%48 scale fold) is REVERTED: it added an
// int-div sequence per fill element and broke the fill/gather overlap that
// made R13 fast (alu 11.2 -> 14.5%). Fill loops here are byte-identical to R13.

typedef unsigned long long u64;

__device__ __forceinline__ u64 fma2(u64 a, u64 b, u64 c) {
    u64 d;
    asm("fma.rn.f32x2 %0, %1, %2, %3;" : "=l"(d) : "l"(a), "l"(b), "l"(c));
    return d;
}
__device__ __forceinline__ u64 pack2(float x, float y) {
    u64 r;
    asm("mov.b64 %0, {%1, %2};" : "=l"(r) : "f"(x), "f"(y));
    return r;
}
__device__ __forceinline__ float2 unpack2(u64 v) {
    float2 f;
    asm("mov.b64 {%0, %1}, %2;" : "=f"(f.x), "=f"(f.y) : "l"(v));
    return f;
}
__device__ __forceinline__ float getc(float4 v, int c) {
    return c == 0 ? v.x : (c == 1 ? v.y : (c == 2 ? v.z : v.w));
}

// Fused weights computed once by prep kernel:
//   W2[d][j] = sum_e w_out[d][e] * fc_w[e][j]    (16 x 32)
//   b2[j]    = fc_b[j] + sum_e b_out[e] * fc_w[e][j]
__device__ float g_W2[16 * 32];
__device__ float g_b2[32];

__global__ void prep_kernel(const float* __restrict__ w_out, const float* __restrict__ b_out,
                            const float* __restrict__ fc_w, const float* __restrict__ fc_b) {
    int i = threadIdx.x;
    if (i < 512) {
        int d = i >> 5, j = i & 31;
        float s = 0.f;
#pragma unroll
        for (int e = 0; e < 16; e++) s += w_out[d * 16 + e] * fc_w[e * 32 + j];
        g_W2[i] = s;
    }
    if (i < 32) {
        float s = fc_b[i];
#pragma unroll
        for (int e = 0; e < 16; e++) s += b_out[e] * fc_w[e * 32 + i];
        g_b2[i] = s;
    }
}

__global__ void __launch_bounds__(128, 4)
face_kernel(const float* __restrict__ node, const int* __restrict__ fids,
            const float* __restrict__ w_in, const float* __restrict__ b_in,
            const float* __restrict__ fco_w, const float* __restrict__ fco_b,
            float* __restrict__ out, int F) {
    __shared__ __align__(16) float s_win[16 * 48];   // packed qkv weights [d][o]
    __shared__ __align__(16) float s_bin[48];
    __shared__ __align__(16) float s_W2[16 * 32];    // fused w_out@fc_w
    __shared__ __align__(16) float s_b2[32];
    __shared__ __align__(16) float s_fco[32 * 32];
    __shared__ __align__(16) float s_fcob[32];
    __shared__ __align__(16) float s_stage[4][8][132];  // [warp][slot][quad*16+chunk*4]

    int tid = threadIdx.x;
    int gt = blockIdx.x * 128 + tid;
    int faceR = gt >> 1;            // real face (may be >= F for tail lanes)
    int h = gt & 1;                 // head index (0 or 1)
    bool valid = faceR < F;
    int face = valid ? faceR : (F - 1);  // clamped for loads

    int lane = tid & 31;
    int wq = lane >> 2;             // quad index within warp (0..7)
    int ql = lane & 3;              // lane within quad

    // ---- gather FIRST: fids + 8 node LDGs in flight before weight fills ----
    int4 Im = *(const int4*)(fids + 4ll * face);
    int ox = __shfl_xor_sync(0xffffffffu, Im.x, 2);
    int oy = __shfl_xor_sync(0xffffffffu, Im.y, 2);
    int oz = __shfl_xor_sync(0xffffffffu, Im.z, 2);
    int ow = __shfl_xor_sync(0xffffffffu, Im.w, 2);
    bool isB = (lane & 2) != 0;
    int IAx = isB ? ox : Im.x, IAy = isB ? oy : Im.y;
    int IAz = isB ? oz : Im.z, IAw = isB ? ow : Im.w;
    int IBx = isB ? Im.x : ox, IBy = isB ? Im.y : oy;
    int IBz = isB ? Im.z : oz, IBw = isB ? Im.w : ow;
    long long co = 4 * ql;          // chunk offset in floats
    float4 r0 = *(const float4*)(node + 16ll * IAx + co);
    float4 r1 = *(const float4*)(node + 16ll * IAz + co);
    float4 r2 = *(const float4*)(node + 16ll * IBx + co);
    float4 r3 = *(const float4*)(node + 16ll * IBz + co);
    float4 r4 = *(const float4*)(node + 16ll * IAy + co);
    float4 r5 = *(const float4*)(node + 16ll * IAw + co);
    float4 r6 = *(const float4*)(node + 16ll * IBy + co);
    float4 r7 = *(const float4*)(node + 16ll * IBw + co);

    // ---- weight smem fills overlap the gather latency (identical to R13) ----
    for (int i = tid; i < 768; i += 128) s_win[i] = w_in[i];
    if (tid < 48) s_bin[tid] = b_in[tid];
    for (int i = tid; i < 512; i += 128) s_W2[i] = g_W2[i];
    if (tid < 32) s_b2[tid] = g_b2[tid];
    for (int i = tid; i < 1024; i += 128) s_fco[i] = fco_w[i];
    if (tid < 32) s_fcob[tid] = fco_b[tid];

    // ---- stage-store + warp-local redistribution (no block barrier needed) ----
    float* st = &s_stage[tid >> 5][0][0];
    {
        int so = wq * 16 + ql * 4;
        *(float4*)(st + 0 * 132 + so) = r0;
        *(float4*)(st + 1 * 132 + so) = r1;
        *(float4*)(st + 2 * 132 + so) = r2;
        *(float4*)(st + 3 * 132 + so) = r3;
        *(float4*)(st + 4 * 132 + so) = r4;
        *(float4*)(st + 5 * 132 + so) = r5;
        *(float4*)(st + 6 * 132 + so) = r6;
        *(float4*)(st + 7 * 132 + so) = r7;
    }
    __syncwarp();
    float4 XA[4], XB[4];
    {
        const float* pa = st + ql * 132 + wq * 16;
        const float* pb = st + (ql + 4) * 132 + wq * 16;
#pragma unroll
        for (int cc = 0; cc < 4; cc++) {
            XA[cc] = *(const float4*)(pa + cc * 4);
            XB[cc] = *(const float4*)(pb + cc * 4);
        }
    }

    __syncthreads();   // weights ready before first use

    // Lane-local token order: 0 = own_a, 1 = own_b, 2 = partner_a, 3 = partner_b.

    // ---- phase 1a: q,k for all 4 tokens (own head), d-outer for weight reuse ----
    u64 q2[4][4], k2[4][4];
    {
        const u64* bq = (const u64*)(s_bin + 8 * h);
        const u64* bk = (const u64*)(s_bin + 16 + 8 * h);
#pragma unroll
        for (int t = 0; t < 4; t++)
#pragma unroll
            for (int j = 0; j < 4; j++) { q2[t][j] = bq[j]; k2[t][j] = bk[j]; }
    }
    {
        const float* wqp = s_win + 8 * h;
        const float* wkp = s_win + 16 + 8 * h;
#pragma unroll
        for (int d = 0; d < 16; d++) {
            ulonglong2 wq0 = *(const ulonglong2*)(wqp + d * 48);
            ulonglong2 wq1 = *(const ulonglong2*)(wqp + d * 48 + 4);
            ulonglong2 wk0 = *(const ulonglong2*)(wkp + d * 48);
            ulonglong2 wk1 = *(const ulonglong2*)(wkp + d * 48 + 4);
            float xa = getc(XA[d >> 2], d & 3);
            float xb = getc(XB[d >> 2], d & 3);
            float fa = __shfl_xor_sync(0xffffffffu, xa, 1);
            float fb = __shfl_xor_sync(0xffffffffu, xb, 1);
            u64 xt[4] = {pack2(xa, xa), pack2(xb, xb), pack2(fa, fa), pack2(fb, fb)};
#pragma unroll
            for (int t = 0; t < 4; t++) {
                q2[t][0] = fma2(xt[t], wq0.x, q2[t][0]);
                q2[t][1] = fma2(xt[t], wq0.y, q2[t][1]);
                q2[t][2] = fma2(xt[t], wq1.x, q2[t][2]);
                q2[t][3] = fma2(xt[t], wq1.y, q2[t][3]);
                k2[t][0] = fma2(xt[t], wk0.x, k2[t][0]);
                k2[t][1] = fma2(xt[t], wk0.y, k2[t][1]);
                k2[t][2] = fma2(xt[t], wk1.x, k2[t][2]);
                k2[t][3] = fma2(xt[t], wk1.y, k2[t][3]);
            }
        }
    }

    // ---- scores + softmax (own head, 4x4; no max-sub, fast reciprocal) ----
    float att[4][4];
    const float RS = 0.35355339059327373f;  // 1/sqrt(8)
#pragma unroll
    for (int qi = 0; qi < 4; qi++) {
#pragma unroll
        for (int ki = 0; ki < 4; ki++) {
            u64 a = fma2(q2[qi][0], k2[ki][0], 0ull);
            a = fma2(q2[qi][1], k2[ki][1], a);
            a = fma2(q2[qi][2], k2[ki][2], a);
            a = fma2(q2[qi][3], k2[ki][3], a);
            float2 p = unpack2(a);
            att[qi][ki] = (p.x + p.y) * RS;
        }
        float e0 = __expf(att[qi][0]);
        float e1 = __expf(att[qi][1]);
        float e2 = __expf(att[qi][2]);
        float e3 = __expf(att[qi][3]);
        float inv = __fdividef(1.0f, e0 + e1 + e2 + e3);
        att[qi][0] = e0 * inv; att[qi][1] = e1 * inv;
        att[qi][2] = e2 * inv; att[qi][3] = e3 * inv;
    }

    // ---- phase 1b: v for all 4 tokens (own head), d-outer ----
    u64 v2[4][4];
    {
        const u64* bv = (const u64*)(s_bin + 32 + 8 * h);
#pragma unroll
        for (int t = 0; t < 4; t++)
#pragma unroll
            for (int j = 0; j < 4; j++) v2[t][j] = bv[j];
    }
    {
        const float* wvp = s_win + 32 + 8 * h;
#pragma unroll
        for (int d = 0; d < 16; d++) {
            ulonglong2 wv0 = *(const ulonglong2*)(wvp + d * 48);
            ulonglong2 wv1 = *(const ulonglong2*)(wvp + d * 48 + 4);
            float xa = getc(XA[d >> 2], d & 3);
            float xb = getc(XB[d >> 2], d & 3);
            float fa = __shfl_xor_sync(0xffffffffu, xa, 1);
            float fb = __shfl_xor_sync(0xffffffffu, xb, 1);
            u64 xt[4] = {pack2(xa, xa), pack2(xb, xb), pack2(fa, fa), pack2(fb, fb)};
#pragma unroll
            for (int t = 0; t < 4; t++) {
                v2[t][0] = fma2(xt[t], wv0.x, v2[t][0]);
                v2[t][1] = fma2(xt[t], wv0.y, v2[t][1]);
                v2[t][2] = fma2(xt[t], wv1.x, v2[t][2]);
                v2[t][3] = fma2(xt[t], wv1.y, v2[t][3]);
            }
        }
    }

    // ---- o = attn @ v for all 4 local query tokens (own head half: 8 dims) ----
    u64 o2[4][4];
#pragma unroll
    for (int qi = 0; qi < 4; qi++) {
#pragma unroll
        for (int j = 0; j < 4; j++) o2[qi][j] = 0ull;
#pragma unroll
        for (int s = 0; s < 4; s++) {
            u64 a2 = pack2(att[qi][s], att[qi][s]);
#pragma unroll
            for (int j = 0; j < 4; j++) o2[qi][j] = fma2(a2, v2[s][j], o2[qi][j]);
        }
    }

    // ---- W2 col-split with PROGRESSIVE o-exchange ----
    u64 acc[4][8];
    {
        const u64* bb = (const u64*)(s_b2 + 16 * h);
#pragma unroll
        for (int t = 0; t < 4; t++)
#pragma unroll
            for (int j = 0; j < 8; j++) acc[t][j] = bb[j];
    }
    {
        const float* wbaseA = s_W2 + (8 * h) * 32 + 16 * h;
#pragma unroll
        for (int dd = 0; dd < 8; dd++) {
            const ulonglong2* wr = (const ulonglong2*)(wbaseA + dd * 32);
            ulonglong2 wa = wr[0], wb = wr[1], wc = wr[2], wd_ = wr[3];
#pragma unroll
            for (int t = 0; t < 4; t++) {
                float2 p = unpack2(o2[t][dd >> 1]);
                float ov = (dd & 1) ? p.y : p.x;
                u64 op = pack2(ov, ov);
                acc[t][0] = fma2(op, wa.x, acc[t][0]);
                acc[t][1] = fma2(op, wa.y, acc[t][1]);
                acc[t][2] = fma2(op, wb.x, acc[t][2]);
                acc[t][3] = fma2(op, wb.y, acc[t][3]);
                acc[t][4] = fma2(op, wc.x, acc[t][4]);
                acc[t][5] = fma2(op, wc.y, acc[t][5]);
                acc[t][6] = fma2(op, wd_.x, acc[t][6]);
                acc[t][7] = fma2(op, wd_.y, acc[t][7]);
            }
        }
    }
    u64 rcv[4][4];
#pragma unroll
    for (int t = 0; t < 4; t++)
#pragma unroll
        for (int j = 0; j < 4; j++)
            rcv[t][j] = __shfl_xor_sync(0xffffffffu, o2[t ^ 2][j], 1);
    {
        const float* wbaseB = s_W2 + (8 * (1 - h)) * 32 + 16 * h;
#pragma unroll
        for (int dd = 0; dd < 8; dd++) {
            const ulonglong2* wr = (const ulonglong2*)(wbaseB + dd * 32);
            ulonglong2 wa = wr[0], wb = wr[1], wc = wr[2], wd_ = wr[3];
#pragma unroll
            for (int t = 0; t < 4; t++) {
                float2 p = unpack2(rcv[t][dd >> 1]);
                float ov = (dd & 1) ? p.y : p.x;
                u64 op = pack2(ov, ov);
                acc[t][0] = fma2(op, wa.x, acc[t][0]);
                acc[t][1] = fma2(op, wa.y, acc[t][1]);
                acc[t][2] = fma2(op, wb.x, acc[t][2]);
                acc[t][3] = fma2(op, wb.y, acc[t][3]);
                acc[t][4] = fma2(op, wc.x, acc[t][4]);
                acc[t][5] = fma2(op, wc.y, acc[t][5]);
                acc[t][6] = fma2(op, wd_.x, acc[t][6]);
                acc[t][7] = fma2(op, wd_.y, acc[t][7]);
            }
        }
    }

    // ---- relu + mean over 4 tokens (thread-local) ----
    u64 pool[8];   // my 16 cols
#pragma unroll
    for (int j = 0; j < 8; j++) {
        float px = 0.f, py = 0.f;
#pragma unroll
        for (int t = 0; t < 4; t++) {
            float2 a = unpack2(acc[t][j]);
            px += fmaxf(a.x, 0.f);
            py += fmaxf(a.y, 0.f);
        }
        pool[j] = pack2(px * 0.25f, py * 0.25f);
    }

    // ---- butterfly: full 32 pooled for own face (xor1), then partner face (xor2) ----
    u64 pown[16];
#pragma unroll
    for (int j = 0; j < 8; j++) {
        u64 other = __shfl_xor_sync(0xffffffffu, pool[j], 1);
        pown[j]     = h ? other : pool[j];
        pown[8 + j] = h ? pool[j] : other;
    }
    u64 poth[16];
#pragma unroll
    for (int j = 0; j < 16; j++)
        poth[j] = __shfl_xor_sync(0xffffffffu, pown[j], 2);

    // ---- fco quad-split: col octet [8c, 8c+8), c = tid&3, for BOTH quad faces ----
    int c = tid & 3;
    u64 accA[4], accB[4];
    {
        const u64* fb = (const u64*)(s_fcob + 8 * c);
#pragma unroll
        for (int p = 0; p < 4; p++) { accA[p] = fb[p]; accB[p] = fb[p]; }
    }
    const float* fch = s_fco + 8 * c;
#pragma unroll
    for (int e = 0; e < 32; e++) {
        float2 ppA = unpack2(pown[e >> 1]);
        float2 ppB = unpack2(poth[e >> 1]);
        float peA = (e & 1) ? ppA.y : ppA.x;
        float peB = (e & 1) ? ppB.y : ppB.x;
        u64 pA2 = pack2(peA, peA);
        u64 pB2 = pack2(peB, peB);
        const ulonglong2* fr = (const ulonglong2*)(fch + e * 32);
        ulonglong2 wa = fr[0], wb = fr[1];
        accA[0] = fma2(pA2, wa.x, accA[0]);
        accA[1] = fma2(pA2, wa.y, accA[1]);
        accA[2] = fma2(pA2, wb.x, accA[2]);
        accA[3] = fma2(pA2, wb.y, accA[3]);
        accB[0] = fma2(pB2, wa.x, accB[0]);
        accB[1] = fma2(pB2, wa.y, accB[1]);
        accB[2] = fma2(pB2, wb.x, accB[2]);
        accB[3] = fma2(pB2, wb.y, accB[3]);
    }

    // ---- stores: face A = my real face; face B = quad partner's face (^1) ----
    int faceB = faceR ^ 1;
    if (valid) {
        float* opA = out + 32ll * faceR + 8 * c;
        float2 a0 = unpack2(accA[0]), a1 = unpack2(accA[1]);
        float2 a2 = unpack2(accA[2]), a3 = unpack2(accA[3]);
        ((float4*)opA)[0] = make_float4(a0.x, a0.y, a1.x, a1.y);
        ((float4*)opA)[1] = make_float4(a2.x, a2.y, a3.x, a3.y);
    }
    if (faceB < F) {
        float* opB = out + 32ll * faceB + 8 * c;
        float2 b0 = unpack2(accB[0]), b1 = unpack2(accB[1]);
        float2 b2 = unpack2(accB[2]), b3 = unpack2(accB[3]);
        ((float4*)opB)[0] = make_float4(b0.x, b0.y, b1.x, b1.y);
        ((float4*)opB)[1] = make_float4(b2.x, b2.y, b3.x, b3.y);
    }
}

extern "C" void kernel_launch(void* const* d_in, const int* in_sizes, int n_in,
                              void* d_out, int out_size) {
    const float* node  = (const float*)d_in[0];
    const int*   fids  = (const int*)d_in[1];
    const float* w_in  = (const float*)d_in[2];
    const float* b_in  = (const float*)d_in[3];
    const float* w_out = (const float*)d_in[4];
    const float* b_out = (const float*)d_in[5];
    const float* fc_w  = (const float*)d_in[6];
    const float* fc_b  = (const float*)d_in[7];
    const float* fco_w = (const float*)d_in[8];
    const float* fco_b = (const float*)d_in[9];

    int F = in_sizes[1] / 4;

    prep_kernel<<<1, 512>>>(w_out, b_out, fc_w, fc_b);

    long long threads = 2ll * F;
    int blocks = (int)((threads + 127) / 128);
    face_kernel<<<blocks, 128>>>(node, fids, w_in, b_in, fco_w, fco_b, (float*)d_out, F);
}

// round 16
// speedup vs baseline: 1.0458x; 1.0149x over previous
#include <cuda_runtime.h>

// PlaneEmbeddingNetwork fused kernel for GB300 (sm_103a), R16 = R13 verbatim.
// Champion kernel (141.4us). Fully fused, 2 threads per face (one per head):
//  - quad-cooperative gather (each LDG.128 touches 8 lines, not 32), staged
//    through a conflict-free smem buffer, issued BEFORE the weight fills so
//    the 12 fill LDG->STS pairs overlap the gather latency
//  - packed fp32 FMA (fma.rn.f32x2) in all four GEMM phases
//  - d-outer loops amortize each shared weight load over 4 tokens
//  - progressive o-exchange W2 (own-head rows before the shuffle, partner
//    rows after) keeps peak live registers at the 128x4 RF budget
//  - thread-local relu+pool, shuffle butterfly, quad-split fco epilogue
// R14/R15 showed this schedule is a fragile local optimum: math trims that
// should be strictly subtractive perturb ptxas scheduling and regress.

typedef unsigned long long u64;

__device__ __forceinline__ u64 fma2(u64 a, u64 b, u64 c) {
    u64 d;
    asm("fma.rn.f32x2 %0, %1, %2, %3;" : "=l"(d) : "l"(a), "l"(b), "l"(c));
    return d;
}
__device__ __forceinline__ u64 pack2(float x, float y) {
    u64 r;
    asm("mov.b64 %0, {%1, %2};" : "=l"(r) : "f"(x), "f"(y));
    return r;
}
__device__ __forceinline__ float2 unpack2(u64 v) {
    float2 f;
    asm("mov.b64 {%0, %1}, %2;" : "=f"(f.x), "=f"(f.y) : "l"(v));
    return f;
}
__device__ __forceinline__ float getc(float4 v, int c) {
    return c == 0 ? v.x : (c == 1 ? v.y : (c == 2 ? v.z : v.w));
}

// Fused weights computed once by prep kernel:
//   W2[d][j] = sum_e w_out[d][e] * fc_w[e][j]    (16 x 32)
//   b2[j]    = fc_b[j] + sum_e b_out[e] * fc_w[e][j]
__device__ float g_W2[16 * 32];
__device__ float g_b2[32];

__global__ void prep_kernel(const float* __restrict__ w_out, const float* __restrict__ b_out,
                            const float* __restrict__ fc_w, const float* __restrict__ fc_b) {
    int i = threadIdx.x;
    if (i < 512) {
        int d = i >> 5, j = i & 31;
        float s = 0.f;
#pragma unroll
        for (int e = 0; e < 16; e++) s += w_out[d * 16 + e] * fc_w[e * 32 + j];
        g_W2[i] = s;
    }
    if (i < 32) {
        float s = fc_b[i];
#pragma unroll
        for (int e = 0; e < 16; e++) s += b_out[e] * fc_w[e * 32 + i];
        g_b2[i] = s;
    }
}

__global__ void __launch_bounds__(128, 4)
face_kernel(const float* __restrict__ node, const int* __restrict__ fids,
            const float* __restrict__ w_in, const float* __restrict__ b_in,
            const float* __restrict__ fco_w, const float* __restrict__ fco_b,
            float* __restrict__ out, int F) {
    __shared__ __align__(16) float s_win[16 * 48];   // packed qkv weights [d][o]
    __shared__ __align__(16) float s_bin[48];
    __shared__ __align__(16) float s_W2[16 * 32];    // fused w_out@fc_w
    __shared__ __align__(16) float s_b2[32];
    __shared__ __align__(16) float s_fco[32 * 32];
    __shared__ __align__(16) float s_fcob[32];
    __shared__ __align__(16) float s_stage[4][8][132];  // [warp][slot][quad*16+chunk*4]

    int tid = threadIdx.x;
    int gt = blockIdx.x * 128 + tid;
    int faceR = gt >> 1;            // real face (may be >= F for tail lanes)
    int h = gt & 1;                 // head index (0 or 1)
    bool valid = faceR < F;
    int face = valid ? faceR : (F - 1);  // clamped for loads

    int lane = tid & 31;
    int wq = lane >> 2;             // quad index within warp (0..7)
    int ql = lane & 3;              // lane within quad

    // ---- gather FIRST: fids + 8 node LDGs in flight before weight fills ----
    int4 Im = *(const int4*)(fids + 4ll * face);
    int ox = __shfl_xor_sync(0xffffffffu, Im.x, 2);
    int oy = __shfl_xor_sync(0xffffffffu, Im.y, 2);
    int oz = __shfl_xor_sync(0xffffffffu, Im.z, 2);
    int ow = __shfl_xor_sync(0xffffffffu, Im.w, 2);
    bool isB = (lane & 2) != 0;
    int IAx = isB ? ox : Im.x, IAy = isB ? oy : Im.y;
    int IAz = isB ? oz : Im.z, IAw = isB ? ow : Im.w;
    int IBx = isB ? Im.x : ox, IBy = isB ? Im.y : oy;
    int IBz = isB ? Im.z : oz, IBw = isB ? Im.w : ow;
    long long co = 4 * ql;          // chunk offset in floats
    float4 r0 = *(const float4*)(node + 16ll * IAx + co);
    float4 r1 = *(const float4*)(node + 16ll * IAz + co);
    float4 r2 = *(const float4*)(node + 16ll * IBx + co);
    float4 r3 = *(const float4*)(node + 16ll * IBz + co);
    float4 r4 = *(const float4*)(node + 16ll * IAy + co);
    float4 r5 = *(const float4*)(node + 16ll * IAw + co);
    float4 r6 = *(const float4*)(node + 16ll * IBy + co);
    float4 r7 = *(const float4*)(node + 16ll * IBw + co);

    // ---- weight smem fills overlap the gather latency ----
    for (int i = tid; i < 768; i += 128) s_win[i] = w_in[i];
    if (tid < 48) s_bin[tid] = b_in[tid];
    for (int i = tid; i < 512; i += 128) s_W2[i] = g_W2[i];
    if (tid < 32) s_b2[tid] = g_b2[tid];
    for (int i = tid; i < 1024; i += 128) s_fco[i] = fco_w[i];
    if (tid < 32) s_fcob[tid] = fco_b[tid];

    // ---- stage-store + warp-local redistribution (no block barrier needed) ----
    float* st = &s_stage[tid >> 5][0][0];
    {
        int so = wq * 16 + ql * 4;
        *(float4*)(st + 0 * 132 + so) = r0;
        *(float4*)(st + 1 * 132 + so) = r1;
        *(float4*)(st + 2 * 132 + so) = r2;
        *(float4*)(st + 3 * 132 + so) = r3;
        *(float4*)(st + 4 * 132 + so) = r4;
        *(float4*)(st + 5 * 132 + so) = r5;
        *(float4*)(st + 6 * 132 + so) = r6;
        *(float4*)(st + 7 * 132 + so) = r7;
    }
    __syncwarp();
    float4 XA[4], XB[4];
    {
        const float* pa = st + ql * 132 + wq * 16;
        const float* pb = st + (ql + 4) * 132 + wq * 16;
#pragma unroll
        for (int cc = 0; cc < 4; cc++) {
            XA[cc] = *(const float4*)(pa + cc * 4);
            XB[cc] = *(const float4*)(pb + cc * 4);
        }
    }

    __syncthreads();   // weights ready before first use

    // Lane-local token order: 0 = own_a, 1 = own_b, 2 = partner_a, 3 = partner_b.

    // ---- phase 1a: q,k for all 4 tokens (own head), d-outer for weight reuse ----
    u64 q2[4][4], k2[4][4];
    {
        const u64* bq = (const u64*)(s_bin + 8 * h);
        const u64* bk = (const u64*)(s_bin + 16 + 8 * h);
#pragma unroll
        for (int t = 0; t < 4; t++)
#pragma unroll
            for (int j = 0; j < 4; j++) { q2[t][j] = bq[j]; k2[t][j] = bk[j]; }
    }
    {
        const float* wqp = s_win + 8 * h;
        const float* wkp = s_win + 16 + 8 * h;
#pragma unroll
        for (int d = 0; d < 16; d++) {
            ulonglong2 wq0 = *(const ulonglong2*)(wqp + d * 48);
            ulonglong2 wq1 = *(const ulonglong2*)(wqp + d * 48 + 4);
            ulonglong2 wk0 = *(const ulonglong2*)(wkp + d * 48);
            ulonglong2 wk1 = *(const ulonglong2*)(wkp + d * 48 + 4);
            float xa = getc(XA[d >> 2], d & 3);
            float xb = getc(XB[d >> 2], d & 3);
            float fa = __shfl_xor_sync(0xffffffffu, xa, 1);
            float fb = __shfl_xor_sync(0xffffffffu, xb, 1);
            u64 xt[4] = {pack2(xa, xa), pack2(xb, xb), pack2(fa, fa), pack2(fb, fb)};
#pragma unroll
            for (int t = 0; t < 4; t++) {
                q2[t][0] = fma2(xt[t], wq0.x, q2[t][0]);
                q2[t][1] = fma2(xt[t], wq0.y, q2[t][1]);
                q2[t][2] = fma2(xt[t], wq1.x, q2[t][2]);
                q2[t][3] = fma2(xt[t], wq1.y, q2[t][3]);
                k2[t][0] = fma2(xt[t], wk0.x, k2[t][0]);
                k2[t][1] = fma2(xt[t], wk0.y, k2[t][1]);
                k2[t][2] = fma2(xt[t], wk1.x, k2[t][2]);
                k2[t][3] = fma2(xt[t], wk1.y, k2[t][3]);
            }
        }
    }

    // ---- scores + softmax (own head, 4x4, lane-local token order) ----
    float att[4][4];
    const float RS = 0.35355339059327373f;  // 1/sqrt(8)
#pragma unroll
    for (int qi = 0; qi < 4; qi++) {
#pragma unroll
        for (int ki = 0; ki < 4; ki++) {
            u64 a = fma2(q2[qi][0], k2[ki][0], 0ull);
            a = fma2(q2[qi][1], k2[ki][1], a);
            a = fma2(q2[qi][2], k2[ki][2], a);
            a = fma2(q2[qi][3], k2[ki][3], a);
            float2 p = unpack2(a);
            att[qi][ki] = (p.x + p.y) * RS;
        }
        float m = fmaxf(fmaxf(att[qi][0], att[qi][1]), fmaxf(att[qi][2], att[qi][3]));
        float e0 = __expf(att[qi][0] - m);
        float e1 = __expf(att[qi][1] - m);
        float e2 = __expf(att[qi][2] - m);
        float e3 = __expf(att[qi][3] - m);
        float inv = 1.0f / (e0 + e1 + e2 + e3);
        att[qi][0] = e0 * inv; att[qi][1] = e1 * inv;
        att[qi][2] = e2 * inv; att[qi][3] = e3 * inv;
    }

    // ---- phase 1b: v for all 4 tokens (own head), d-outer ----
    u64 v2[4][4];
    {
        const u64* bv = (const u64*)(s_bin + 32 + 8 * h);
#pragma unroll
        for (int t = 0; t < 4; t++)
#pragma unroll
            for (int j = 0; j < 4; j++) v2[t][j] = bv[j];
    }
    {
        const float* wvp = s_win + 32 + 8 * h;
#pragma unroll
        for (int d = 0; d < 16; d++) {
            ulonglong2 wv0 = *(const ulonglong2*)(wvp + d * 48);
            ulonglong2 wv1 = *(const ulonglong2*)(wvp + d * 48 + 4);
            float xa = getc(XA[d >> 2], d & 3);
            float xb = getc(XB[d >> 2], d & 3);
            float fa = __shfl_xor_sync(0xffffffffu, xa, 1);
            float fb = __shfl_xor_sync(0xffffffffu, xb, 1);
            u64 xt[4] = {pack2(xa, xa), pack2(xb, xb), pack2(fa, fa), pack2(fb, fb)};
#pragma unroll
            for (int t = 0; t < 4; t++) {
                v2[t][0] = fma2(xt[t], wv0.x, v2[t][0]);
                v2[t][1] = fma2(xt[t], wv0.y, v2[t][1]);
                v2[t][2] = fma2(xt[t], wv1.x, v2[t][2]);
                v2[t][3] = fma2(xt[t], wv1.y, v2[t][3]);
            }
        }
    }

    // ---- o = attn @ v for all 4 local query tokens (own head half: 8 dims) ----
    u64 o2[4][4];
#pragma unroll
    for (int qi = 0; qi < 4; qi++) {
#pragma unroll
        for (int j = 0; j < 4; j++) o2[qi][j] = 0ull;
#pragma unroll
        for (int s = 0; s < 4; s++) {
            u64 a2 = pack2(att[qi][s], att[qi][s]);
#pragma unroll
            for (int j = 0; j < 4; j++) o2[qi][j] = fma2(a2, v2[s][j], o2[qi][j]);
        }
    }

    // ---- W2 col-split with PROGRESSIVE o-exchange ----
    u64 acc[4][8];
    {
        const u64* bb = (const u64*)(s_b2 + 16 * h);
#pragma unroll
        for (int t = 0; t < 4; t++)
#pragma unroll
            for (int j = 0; j < 8; j++) acc[t][j] = bb[j];
    }
    {
        const float* wbaseA = s_W2 + (8 * h) * 32 + 16 * h;
#pragma unroll
        for (int dd = 0; dd < 8; dd++) {
            const ulonglong2* wr = (const ulonglong2*)(wbaseA + dd * 32);
            ulonglong2 wa = wr[0], wb = wr[1], wc = wr[2], wd_ = wr[3];
#pragma unroll
            for (int t = 0; t < 4; t++) {
                float2 p = unpack2(o2[t][dd >> 1]);
                float ov = (dd & 1) ? p.y : p.x;
                u64 op = pack2(ov, ov);
                acc[t][0] = fma2(op, wa.x, acc[t][0]);
                acc[t][1] = fma2(op, wa.y, acc[t][1]);
                acc[t][2] = fma2(op, wb.x, acc[t][2]);
                acc[t][3] = fma2(op, wb.y, acc[t][3]);
                acc[t][4] = fma2(op, wc.x, acc[t][4]);
                acc[t][5] = fma2(op, wc.y, acc[t][5]);
                acc[t][6] = fma2(op, wd_.x, acc[t][6]);
                acc[t][7] = fma2(op, wd_.y, acc[t][7]);
            }
        }
    }
    u64 rcv[4][4];
#pragma unroll
    for (int t = 0; t < 4; t++)
#pragma unroll
        for (int j = 0; j < 4; j++)
            rcv[t][j] = __shfl_xor_sync(0xffffffffu, o2[t ^ 2][j], 1);
    {
        const float* wbaseB = s_W2 + (8 * (1 - h)) * 32 + 16 * h;
#pragma unroll
        for (int dd = 0; dd < 8; dd++) {
            const ulonglong2* wr = (const ulonglong2*)(wbaseB + dd * 32);
            ulonglong2 wa = wr[0], wb = wr[1], wc = wr[2], wd_ = wr[3];
#pragma unroll
            for (int t = 0; t < 4; t++) {
                float2 p = unpack2(rcv[t][dd >> 1]);
                float ov = (dd & 1) ? p.y : p.x;
                u64 op = pack2(ov, ov);
                acc[t][0] = fma2(op, wa.x, acc[t][0]);
                acc[t][1] = fma2(op, wa.y, acc[t][1]);
                acc[t][2] = fma2(op, wb.x, acc[t][2]);
                acc[t][3] = fma2(op, wb.y, acc[t][3]);
                acc[t][4] = fma2(op, wc.x, acc[t][4]);
                acc[t][5] = fma2(op, wc.y, acc[t][5]);
                acc[t][6] = fma2(op, wd_.x, acc[t][6]);
                acc[t][7] = fma2(op, wd_.y, acc[t][7]);
            }
        }
    }

    // ---- relu + mean over 4 tokens (thread-local) ----
    u64 pool[8];   // my 16 cols
#pragma unroll
    for (int j = 0; j < 8; j++) {
        float px = 0.f, py = 0.f;
#pragma unroll
        for (int t = 0; t < 4; t++) {
            float2 a = unpack2(acc[t][j]);
            px += fmaxf(a.x, 0.f);
            py += fmaxf(a.y, 0.f);
        }
        pool[j] = pack2(px * 0.25f, py * 0.25f);
    }

    // ---- butterfly: full 32 pooled for own face (xor1), then partner face (xor2) ----
    u64 pown[16];
#pragma unroll
    for (int j = 0; j < 8; j++) {
        u64 other = __shfl_xor_sync(0xffffffffu, pool[j], 1);
        pown[j]     = h ? other : pool[j];
        pown[8 + j] = h ? pool[j] : other;
    }
    u64 poth[16];
#pragma unroll
    for (int j = 0; j < 16; j++)
        poth[j] = __shfl_xor_sync(0xffffffffu, pown[j], 2);

    // ---- fco quad-split: col octet [8c, 8c+8), c = tid&3, for BOTH quad faces ----
    int c = tid & 3;
    u64 accA[4], accB[4];
    {
        const u64* fb = (const u64*)(s_fcob + 8 * c);
#pragma unroll
        for (int p = 0; p < 4; p++) { accA[p] = fb[p]; accB[p] = fb[p]; }
    }
    const float* fch = s_fco + 8 * c;
#pragma unroll
    for (int e = 0; e < 32; e++) {
        float2 ppA = unpack2(pown[e >> 1]);
        float2 ppB = unpack2(poth[e >> 1]);
        float peA = (e & 1) ? ppA.y : ppA.x;
        float peB = (e & 1) ? ppB.y : ppB.x;
        u64 pA2 = pack2(peA, peA);
        u64 pB2 = pack2(peB, peB);
        const ulonglong2* fr = (const ulonglong2*)(fch + e * 32);
        ulonglong2 wa = fr[0], wb = fr[1];
        accA[0] = fma2(pA2, wa.x, accA[0]);
        accA[1] = fma2(pA2, wa.y, accA[1]);
        accA[2] = fma2(pA2, wb.x, accA[2]);
        accA[3] = fma2(pA2, wb.y, accA[3]);
        accB[0] = fma2(pB2, wa.x, accB[0]);
        accB[1] = fma2(pB2, wa.y, accB[1]);
        accB[2] = fma2(pB2, wb.x, accB[2]);
        accB[3] = fma2(pB2, wb.y, accB[3]);
    }

    // ---- stores: face A = my real face; face B = quad partner's face (^1) ----
    int faceB = faceR ^ 1;
    if (valid) {
        float* opA = out + 32ll * faceR + 8 * c;
        float2 a0 = unpack2(accA[0]), a1 = unpack2(accA[1]);
        float2 a2 = unpack2(accA[2]), a3 = unpack2(accA[3]);
        ((float4*)opA)[0] = make_float4(a0.x, a0.y, a1.x, a1.y);
        ((float4*)opA)[1] = make_float4(a2.x, a2.y, a3.x, a3.y);
    }
    if (faceB < F) {
        float* opB = out + 32ll * faceB + 8 * c;
        float2 b0 = unpack2(accB[0]), b1 = unpack2(accB[1]);
        float2 b2 = unpack2(accB[2]), b3 = unpack2(accB[3]);
        ((float4*)opB)[0] = make_float4(b0.x, b0.y, b1.x, b1.y);
        ((float4*)opB)[1] = make_float4(b2.x, b2.y, b3.x, b3.y);
    }
}

extern "C" void kernel_launch(void* const* d_in, const int* in_sizes, int n_in,
                              void* d_out, int out_size) {
    const float* node  = (const float*)d_in[0];
    const int*   fids  = (const int*)d_in[1];
    const float* w_in  = (const float*)d_in[2];
    const float* b_in  = (const float*)d_in[3];
    const float* w_out = (const float*)d_in[4];
    const float* b_out = (const float*)d_in[5];
    const float* fc_w  = (const float*)d_in[6];
    const float* fc_b  = (const float*)d_in[7];
    const float* fco_w = (const float*)d_in[8];
    const float* fco_b = (const float*)d_in[9];

    int F = in_sizes[1] / 4;

    prep_kernel<<<1, 512>>>(w_out, b_out, fc_w, fc_b);

    long long threads = 2ll * F;
    int blocks = (int)((threads + 127) / 128);
    face_kernel<<<blocks, 128>>>(node, fids, w_in, b_in, fco_w, fco_b, (float*)d_out, F);
}